// round 1
// baseline (speedup 1.0000x reference)
#include <cuda_runtime.h>
#include <cuda_bf16.h>

// Problem constants
#define BATCH 8
#define CDIM 512
#define LDIM 4096
#define HEADS 8
#define DHEAD 64
#define HID 512            // HEADS*DHEAD
#define QKV_ROWS 1536      // 3*HID
#define CSPLIT 32          // n-splits for context partials

// Scratch (device globals; no allocation allowed)
__device__ float g_qkv[(size_t)BATCH * QKV_ROWS * LDIM];           // 201 MB
__device__ float g_part[(size_t)CSPLIT * BATCH * HEADS * DHEAD * DHEAD]; // 33.5 MB
__device__ float g_ctx[(size_t)BATCH * HEADS * DHEAD * DHEAD];     // 1 MB
__device__ float g_M[(size_t)BATCH * HID * HID];                   // 8 MB

// ---------------------------------------------------------------------------
// Tiled FP32 SGEMM: C[M,N] = A[M,K] @ B[K,N] (+bias per row), batched via strides.
// BM=BN=128, BK=8, 256 threads, 8x8 register tile per thread.
// Requires M%128==0, N%128==0, K%8==0 (true for all our shapes).
// ---------------------------------------------------------------------------
#define BM 128
#define BN 128
#define BKK 8
#define TM 8
#define TN 8

__global__ __launch_bounds__(256) void sgemm_kernel(
    const float* __restrict__ A, const float* __restrict__ B, float* __restrict__ C,
    int M, int N, int K,
    long long sA, long long sB, long long sC,
    const float* __restrict__ bias)
{
    const int batch = blockIdx.z;
    A += (long long)batch * sA;
    B += (long long)batch * sB;
    C += (long long)batch * sC;

    const int bm = blockIdx.y * BM;
    const int bn = blockIdx.x * BN;

    __shared__ float As[BKK][BM];
    __shared__ float Bs[BKK][BN];

    const int tid = threadIdx.x;
    const int tx = tid & 15;   // 16 col groups
    const int ty = tid >> 4;   // 16 row groups

    // A tile load mapping: 128 rows x 8 k -> one float4 per thread
    const int arow = tid >> 1;
    const int acol = (tid & 1) * 4;
    // B tile load mapping: 8 rows x 128 cols -> one float4 per thread
    const int brow = tid >> 5;
    const int bcol = (tid & 31) * 4;

    float acc[TM][TN];
#pragma unroll
    for (int i = 0; i < TM; i++)
#pragma unroll
        for (int j = 0; j < TN; j++) acc[i][j] = 0.0f;

    for (int k0 = 0; k0 < K; k0 += BKK) {
        float4 a4 = *(const float4*)(A + (long long)(bm + arow) * K + (k0 + acol));
        As[acol + 0][arow] = a4.x;
        As[acol + 1][arow] = a4.y;
        As[acol + 2][arow] = a4.z;
        As[acol + 3][arow] = a4.w;
        float4 b4 = *(const float4*)(B + (long long)(k0 + brow) * N + (bn + bcol));
        *(float4*)(&Bs[brow][bcol]) = b4;
        __syncthreads();

#pragma unroll
        for (int kk = 0; kk < BKK; kk++) {
            float ar[TM], br[TN];
#pragma unroll
            for (int i = 0; i < TM; i += 4) {
                float4 t = *(const float4*)(&As[kk][ty * TM + i]);
                ar[i] = t.x; ar[i + 1] = t.y; ar[i + 2] = t.z; ar[i + 3] = t.w;
            }
#pragma unroll
            for (int j = 0; j < TN; j += 4) {
                float4 t = *(const float4*)(&Bs[kk][tx * TN + j]);
                br[j] = t.x; br[j + 1] = t.y; br[j + 2] = t.z; br[j + 3] = t.w;
            }
#pragma unroll
            for (int i = 0; i < TM; i++)
#pragma unroll
                for (int j = 0; j < TN; j++)
                    acc[i][j] = fmaf(ar[i], br[j], acc[i][j]);
        }
        __syncthreads();
    }

#pragma unroll
    for (int i = 0; i < TM; i++) {
        const int row = bm + ty * TM + i;
        const float bv = bias ? bias[row] : 0.0f;
#pragma unroll
        for (int j = 0; j < TN; j += 4) {
            float4 v;
            v.x = acc[i][j + 0] + bv;
            v.y = acc[i][j + 1] + bv;
            v.z = acc[i][j + 2] + bv;
            v.w = acc[i][j + 3] + bv;
            *(float4*)(C + (long long)row * N + bn + tx * TN + j) = v;
        }
    }
}

// ---------------------------------------------------------------------------
// Row softmax over L=4096 on k rows (rows 512..1023 of each batch's qkv), in place
// ---------------------------------------------------------------------------
__global__ __launch_bounds__(256) void softmax_kernel()
{
    const int row = blockIdx.x;           // 0..BATCH*HID-1
    const int b = row >> 9;               // /512
    const int r = row & 511;
    float* p = g_qkv + (long long)b * QKV_ROWS * LDIM + (long long)(HID + r) * LDIM;

    const int tid = threadIdx.x;
    __shared__ float red[256];

    float4 v[4];
#pragma unroll
    for (int i = 0; i < 4; i++)
        v[i] = *(const float4*)(p + i * 1024 + tid * 4);

    float vmax = -1e30f;
#pragma unroll
    for (int i = 0; i < 4; i++) {
        vmax = fmaxf(vmax, fmaxf(fmaxf(v[i].x, v[i].y), fmaxf(v[i].z, v[i].w)));
    }
    red[tid] = vmax;
    __syncthreads();
    for (int s = 128; s > 0; s >>= 1) {
        if (tid < s) red[tid] = fmaxf(red[tid], red[tid + s]);
        __syncthreads();
    }
    vmax = red[0];
    __syncthreads();

    float lsum = 0.0f;
#pragma unroll
    for (int i = 0; i < 4; i++) {
        v[i].x = expf(v[i].x - vmax); lsum += v[i].x;
        v[i].y = expf(v[i].y - vmax); lsum += v[i].y;
        v[i].z = expf(v[i].z - vmax); lsum += v[i].z;
        v[i].w = expf(v[i].w - vmax); lsum += v[i].w;
    }
    red[tid] = lsum;
    __syncthreads();
    for (int s = 128; s > 0; s >>= 1) {
        if (tid < s) red[tid] += red[tid + s];
        __syncthreads();
    }
    const float inv = 1.0f / red[0];

#pragma unroll
    for (int i = 0; i < 4; i++) {
        v[i].x *= inv; v[i].y *= inv; v[i].z *= inv; v[i].w *= inv;
        *(float4*)(p + i * 1024 + tid * 4) = v[i];
    }
}

// ---------------------------------------------------------------------------
// Context partials: part[split][bh][d][e] = sum over n-chunk of ksoft[d,n]*v[e,n]
// grid: (CSPLIT, 64), 256 threads, each thread 4x4 outputs.
// ---------------------------------------------------------------------------
__global__ __launch_bounds__(256) void context_partial_kernel()
{
    const int split = blockIdx.x;         // 0..CSPLIT-1
    const int bh = blockIdx.y;            // 0..63
    const int b = bh >> 3, h = bh & 7;

    const float* kbase = g_qkv + (long long)b * QKV_ROWS * LDIM + (long long)(HID + h * DHEAD) * LDIM;
    const float* vbase = g_qkv + (long long)b * QKV_ROWS * LDIM + (long long)(2 * HID + h * DHEAD) * LDIM;

    __shared__ float Ks[64][65];
    __shared__ float Vs[64][65];

    const int tid = threadIdx.x;
    const int td = (tid >> 4) * 4;   // d base
    const int te = (tid & 15) * 4;   // e base

    float acc[4][4];
#pragma unroll
    for (int i = 0; i < 4; i++)
#pragma unroll
        for (int j = 0; j < 4; j++) acc[i][j] = 0.0f;

    const int chunk = LDIM / CSPLIT;      // 128
    for (int sub = 0; sub < chunk / 64; sub++) {
        const int n0 = split * chunk + sub * 64;
        // load 64x64 tiles (1024 float4 each)
        for (int i = tid; i < 1024; i += 256) {
            const int r = i >> 4, c = (i & 15) * 4;
            float4 kv = *(const float4*)(kbase + (long long)r * LDIM + n0 + c);
            Ks[r][c] = kv.x; Ks[r][c + 1] = kv.y; Ks[r][c + 2] = kv.z; Ks[r][c + 3] = kv.w;
            float4 vv = *(const float4*)(vbase + (long long)r * LDIM + n0 + c);
            Vs[r][c] = vv.x; Vs[r][c + 1] = vv.y; Vs[r][c + 2] = vv.z; Vs[r][c + 3] = vv.w;
        }
        __syncthreads();

#pragma unroll 8
        for (int n = 0; n < 64; n++) {
            float kr[4], vr[4];
#pragma unroll
            for (int i = 0; i < 4; i++) kr[i] = Ks[td + i][n];
#pragma unroll
            for (int j = 0; j < 4; j++) vr[j] = Vs[te + j][n];
#pragma unroll
            for (int i = 0; i < 4; i++)
#pragma unroll
                for (int j = 0; j < 4; j++)
                    acc[i][j] = fmaf(kr[i], vr[j], acc[i][j]);
        }
        __syncthreads();
    }

    float* pout = g_part + ((long long)split * 64 + bh) * (DHEAD * DHEAD);
#pragma unroll
    for (int i = 0; i < 4; i++)
#pragma unroll
        for (int j = 0; j < 4; j++)
            pout[(td + i) * DHEAD + (te + j)] = acc[i][j];
}

// Deterministic reduction of partials -> g_ctx
__global__ __launch_bounds__(256) void reduce_ctx_kernel()
{
    const int i = blockIdx.x * blockDim.x + threadIdx.x;  // 0..262143
    const int total = BATCH * HEADS * DHEAD * DHEAD;
    if (i < total) {
        float s = 0.0f;
#pragma unroll
        for (int sp = 0; sp < CSPLIT; sp++)
            s += g_part[(long long)sp * total + i];
        g_ctx[i] = s;
    }
}

// ---------------------------------------------------------------------------
// Fold w_out with ctx: M_b[o, h*64+d] = sum_e w_out[o, h*64+e] * ctx[b,h,d,e]
// grid: (8 o-chunks, 64 bh), 256 threads
// ---------------------------------------------------------------------------
__global__ __launch_bounds__(256) void fold_kernel(const float* __restrict__ w_out)
{
    const int oc = blockIdx.x;   // o chunk of 64
    const int bh = blockIdx.y;
    const int b = bh >> 3, h = bh & 7;

    __shared__ float cs[64][65];  // ctx[d][e]
    __shared__ float ws[64][65];  // w_out[oc*64+r][h*64+e]

    const int tid = threadIdx.x;
    for (int i = tid; i < 4096; i += 256) {
        const int d = i >> 6, e = i & 63;
        cs[d][e] = g_ctx[((long long)bh * 64 + d) * 64 + e];
    }
    for (int i = tid; i < 4096; i += 256) {
        const int r = i >> 6, e = i & 63;
        ws[r][e] = w_out[(long long)(oc * 64 + r) * CDIM + h * 64 + e];
    }
    __syncthreads();

    const int d = tid & 63;
    const int r0 = (tid >> 6) * 16;
    for (int rr = 0; rr < 16; rr++) {
        float s = 0.0f;
#pragma unroll 8
        for (int e = 0; e < 64; e++)
            s = fmaf(ws[r0 + rr][e], cs[d][e], s);
        g_M[((long long)b * HID + oc * 64 + r0 + rr) * HID + h * 64 + d] = s;
    }
}

// ---------------------------------------------------------------------------
extern "C" void kernel_launch(void* const* d_in, const int* in_sizes, int n_in,
                              void* d_out, int out_size)
{
    const float* x     = (const float*)d_in[0];   // [8, 512, 4096]
    const float* w_qkv = (const float*)d_in[1];   // [1536, 512]
    const float* w_out = (const float*)d_in[2];   // [512, 512]
    const float* b_out = (const float*)d_in[3];   // [512]
    float* out = (float*)d_out;                   // [8, 512, 4096]

    float *p_qkv, *p_M;
    cudaGetSymbolAddress((void**)&p_qkv, g_qkv);
    cudaGetSymbolAddress((void**)&p_M, g_M);

    // 1) qkv = w_qkv @ x_b   (A shared across batches)
    {
        dim3 grid(LDIM / BN, QKV_ROWS / BM, BATCH);
        sgemm_kernel<<<grid, 256>>>(w_qkv, x, p_qkv,
                                    QKV_ROWS, LDIM, CDIM,
                                    0LL, (long long)CDIM * LDIM, (long long)QKV_ROWS * LDIM,
                                    nullptr);
    }

    // 2) softmax over L on k rows
    softmax_kernel<<<BATCH * HID, 256>>>();

    // 3) context partials + deterministic reduce
    context_partial_kernel<<<dim3(CSPLIT, BATCH * HEADS), 256>>>();
    {
        const int total = BATCH * HEADS * DHEAD * DHEAD;
        reduce_ctx_kernel<<<(total + 255) / 256, 256>>>();
    }

    // 4) fold w_out with context -> per-batch M
    fold_kernel<<<dim3(8, BATCH * HEADS), 256>>>(w_out);

    // 5) out = M_b @ q_b + b_out
    {
        dim3 grid(LDIM / BN, HID / BM, BATCH);
        sgemm_kernel<<<grid, 256>>>(p_M, p_qkv, out,
                                    HID, LDIM, HID,
                                    (long long)HID * HID, (long long)QKV_ROWS * LDIM, (long long)HID * LDIM,
                                    b_out);
    }
}

// round 3
// speedup vs baseline: 2.4546x; 2.4546x over previous
#include <cuda_runtime.h>
#include <cuda_bf16.h>
#include <cstdint>

// Problem constants
#define BATCH 8
#define CDIM 512
#define LDIM 4096
#define HEADS 8
#define DHEAD 64
#define HID 512            // HEADS*DHEAD
#define QKV_ROWS 1536      // 3*HID
#define CSPLIT 32          // n-splits for context partials

// ---------------------------------------------------------------------------
// Scratch (device globals; no allocation allowed)
// ---------------------------------------------------------------------------
__device__ float g_qkv[(size_t)BATCH * QKV_ROWS * LDIM];
__device__ __nv_bfloat16 g_xt_hi[(size_t)BATCH * LDIM * CDIM];
__device__ __nv_bfloat16 g_xt_lo[(size_t)BATCH * LDIM * CDIM];
__device__ __nv_bfloat16 g_qt_hi[(size_t)BATCH * LDIM * HID];
__device__ __nv_bfloat16 g_qt_lo[(size_t)BATCH * LDIM * HID];
__device__ __nv_bfloat16 g_w_hi[(size_t)QKV_ROWS * CDIM];
__device__ __nv_bfloat16 g_w_lo[(size_t)QKV_ROWS * CDIM];
__device__ float g_part[(size_t)CSPLIT * BATCH * HEADS * DHEAD * DHEAD];
__device__ float g_ctx[(size_t)BATCH * HEADS * DHEAD * DHEAD];
__device__ float g_M[(size_t)BATCH * HID * HID];
__device__ __nv_bfloat16 g_M_hi[(size_t)BATCH * HID * HID];
__device__ __nv_bfloat16 g_M_lo[(size_t)BATCH * HID * HID];

// ---------------------------------------------------------------------------
// PTX helpers (baseline sm_103 — NO tcgen05)
// ---------------------------------------------------------------------------
__device__ __forceinline__ uint32_t smem_to_u32(const void* smem_ptr) {
    uint32_t addr;
    asm("{ .reg .u64 tmp; cvta.to.shared.u64 tmp, %1; cvt.u32.u64 %0, tmp; }"
        : "=r"(addr) : "l"(smem_ptr));
    return addr;
}

#define SMEM_SWIZZLE_128B(byte_offset) \
    ((uint32_t)(byte_offset) ^ ((((uint32_t)(byte_offset)) >> 3) & 0x70u))

__device__ __forceinline__ void cp_async16(uint32_t dst, const void* src) {
    asm volatile("cp.async.cg.shared.global [%0], [%1], 16;"
                 :: "r"(dst), "l"(src) : "memory");
}
#define CP_ASYNC_COMMIT() asm volatile("cp.async.commit_group;" ::: "memory")
#define CP_ASYNC_WAIT(n)  asm volatile("cp.async.wait_group %0;" :: "n"(n) : "memory")

__device__ __forceinline__ void ldsm4(uint32_t* r, uint32_t addr) {
    asm volatile("ldmatrix.sync.aligned.m8n8.x4.shared.b16 {%0,%1,%2,%3}, [%4];"
                 : "=r"(r[0]), "=r"(r[1]), "=r"(r[2]), "=r"(r[3]) : "r"(addr));
}

__device__ __forceinline__ void mma_bf16(float* c, const uint32_t* a, const uint32_t* b) {
    asm volatile(
        "mma.sync.aligned.m16n8k16.row.col.f32.bf16.bf16.f32 "
        "{%0,%1,%2,%3}, {%4,%5,%6,%7}, {%8,%9}, {%0,%1,%2,%3};"
        : "+f"(c[0]), "+f"(c[1]), "+f"(c[2]), "+f"(c[3])
        : "r"(a[0]), "r"(a[1]), "r"(a[2]), "r"(a[3]), "r"(b[0]), "r"(b[1]));
}

// ---------------------------------------------------------------------------
// Split-bf16 HMMA GEMM: C[M,N] = A[M,K] @ B[N,K]^T (+row bias)
// A ~ Ahi+Alo, B ~ Bhi+Blo; fp32 accumulation; 3-term compensated product.
// Tile 128x128, BK=64, 256 threads (2x4 warps, warp tile 64x32).
// 2-stage cp.async pipeline; 64KB per stage (4 sub-tiles of 16KB).
// ---------------------------------------------------------------------------
#define STAGE_BYTES 65536
#define OFF_AHI 0
#define OFF_ALO 16384
#define OFF_BHI 32768
#define OFF_BLO 49152
#define GEMM_SMEM (2 * STAGE_BYTES)

__global__ __launch_bounds__(256, 1)
void mma_gemm_kernel(const __nv_bfloat16* __restrict__ Ahi,
                     const __nv_bfloat16* __restrict__ Alo,
                     const __nv_bfloat16* __restrict__ Bhi,
                     const __nv_bfloat16* __restrict__ Blo,
                     float* __restrict__ C,
                     int M, int N, int K,
                     long long sA, long long sB, long long sC,
                     const float* __restrict__ bias)
{
    extern __shared__ char smem[];
    const uint32_t smem_base = smem_to_u32(smem);

    const int tid = threadIdx.x;
    const int wid = tid >> 5;
    const int lane = tid & 31;
    const int warp_m = wid >> 2;       // 0..1  (64 rows each)
    const int warp_n = wid & 3;        // 0..3  (32 cols each)

    const int b = blockIdx.z;
    Ahi += (long long)b * sA;  Alo += (long long)b * sA;
    Bhi += (long long)b * sB;  Blo += (long long)b * sB;
    C   += (long long)b * sC;

    const int bm = blockIdx.y * 128;
    const int bn = blockIdx.x * 128;

    float acc[4][4][4];
#pragma unroll
    for (int i = 0; i < 4; i++)
#pragma unroll
        for (int j = 0; j < 4; j++)
#pragma unroll
            for (int r = 0; r < 4; r++) acc[i][j][r] = 0.0f;

    const int nchunk = K >> 6;   // K/64

    // --- chunk loader ---
    auto load_chunk = [&](int ch, int stage) {
        const int k0 = ch << 6;
        const uint32_t sb = smem_base + stage * STAGE_BYTES;
#pragma unroll
        for (int it = 0; it < 4; it++) {
            const int g = it * 256 + tid;     // 0..1023 granules (16B each)
            const int row = g >> 3;
            const int gr = g & 7;
            const uint32_t sw = SMEM_SWIZZLE_128B(row * 128 + gr * 16);
            const long long aoff = (long long)(bm + row) * K + k0 + gr * 8;
            const long long boff = (long long)(bn + row) * K + k0 + gr * 8;
            cp_async16(sb + OFF_AHI + sw, Ahi + aoff);
            cp_async16(sb + OFF_ALO + sw, Alo + aoff);
            cp_async16(sb + OFF_BHI + sw, Bhi + boff);
            cp_async16(sb + OFF_BLO + sw, Blo + boff);
        }
        CP_ASYNC_COMMIT();
    };

    load_chunk(0, 0);

    for (int ch = 0; ch < nchunk; ch++) {
        if (ch + 1 < nchunk) {
            load_chunk(ch + 1, (ch + 1) & 1);
            CP_ASYNC_WAIT(1);
        } else {
            CP_ASYNC_WAIT(0);
        }
        __syncthreads();

        const uint32_t sb = smem_base + (ch & 1) * STAGE_BYTES;
#pragma unroll
        for (int ks = 0; ks < 4; ks++) {
            // B fragments (hi & lo): 4 n8 tiles per warp
            uint32_t bhi[8], blo[8];
#pragma unroll
            for (int p = 0; p < 2; p++) {
                const int r = warp_n * 32 + p * 16 + ((lane >> 4) & 1) * 8 + (lane & 7);
                const int cb = ks * 32 + ((lane >> 3) & 1) * 16;
                const uint32_t adr = sb + OFF_BHI + SMEM_SWIZZLE_128B(r * 128 + cb);
                ldsm4(bhi + p * 4, adr);
                ldsm4(blo + p * 4, adr + (OFF_BLO - OFF_BHI));
            }
#pragma unroll
            for (int i = 0; i < 4; i++) {
                const int r = warp_m * 64 + i * 16 + ((lane >> 3) & 1) * 8 + (lane & 7);
                const int cb = ks * 32 + ((lane >> 4) & 1) * 16;
                const uint32_t adr = sb + OFF_AHI + SMEM_SWIZZLE_128B(r * 128 + cb);
                uint32_t ahi[4], alo[4];
                ldsm4(ahi, adr);
                ldsm4(alo, adr + (OFF_ALO - OFF_AHI));
#pragma unroll
                for (int j = 0; j < 4; j++) {
                    const uint32_t* bh = bhi + (j >> 1) * 4 + (j & 1) * 2;
                    const uint32_t* bl = blo + (j >> 1) * 4 + (j & 1) * 2;
                    mma_bf16(acc[i][j], ahi, bh);
                    mma_bf16(acc[i][j], ahi, bl);
                    mma_bf16(acc[i][j], alo, bh);
                }
            }
        }
        __syncthreads();
    }

    // Epilogue: direct float2 stores (+bias)
#pragma unroll
    for (int i = 0; i < 4; i++) {
        const int m0 = bm + warp_m * 64 + i * 16 + (lane >> 2);
        const float bv0 = bias ? bias[m0] : 0.0f;
        const float bv1 = bias ? bias[m0 + 8] : 0.0f;
#pragma unroll
        for (int j = 0; j < 4; j++) {
            const int n0 = bn + warp_n * 32 + j * 8 + (lane & 3) * 2;
            float2 v0, v1;
            v0.x = acc[i][j][0] + bv0;  v0.y = acc[i][j][1] + bv0;
            v1.x = acc[i][j][2] + bv1;  v1.y = acc[i][j][3] + bv1;
            *(float2*)(C + (long long)m0 * N + n0) = v0;
            *(float2*)(C + (long long)(m0 + 8) * N + n0) = v1;
        }
    }
}

// ---------------------------------------------------------------------------
// Transpose + split-convert: in fp32 [R, L] -> out_hi/out_lo bf16 [L, R]
// ---------------------------------------------------------------------------
__global__ __launch_bounds__(256) void transpose_convert_kernel(
    const float* __restrict__ in,
    __nv_bfloat16* __restrict__ out_hi, __nv_bfloat16* __restrict__ out_lo,
    int R, int L, long long inStride, long long outStride)
{
    const int b = blockIdx.z;
    in += (long long)b * inStride;
    out_hi += (long long)b * outStride;
    out_lo += (long long)b * outStride;

    __shared__ float t[32][33];
    const int r0 = blockIdx.y * 32;
    const int c0 = blockIdx.x * 32;
    const int tx = threadIdx.x & 31;
    const int ty = threadIdx.x >> 5;

#pragma unroll
    for (int i = 0; i < 4; i++)
        t[ty + i * 8][tx] = in[(long long)(r0 + ty + i * 8) * L + c0 + tx];
    __syncthreads();
#pragma unroll
    for (int i = 0; i < 4; i++) {
        const float v = t[tx][ty + i * 8];
        const __nv_bfloat16 hi = __float2bfloat16(v);
        const float lo = v - __bfloat162float(hi);
        const long long o = (long long)(c0 + ty + i * 8) * R + r0 + tx;
        out_hi[o] = hi;
        out_lo[o] = __float2bfloat16(lo);
    }
}

// Plain split-convert
__global__ __launch_bounds__(256) void convert_split_kernel(
    const float* __restrict__ in,
    __nv_bfloat16* __restrict__ hi, __nv_bfloat16* __restrict__ lo, int n)
{
    const int i = blockIdx.x * blockDim.x + threadIdx.x;
    if (i < n) {
        const float v = in[i];
        const __nv_bfloat16 h = __float2bfloat16(v);
        hi[i] = h;
        lo[i] = __float2bfloat16(v - __bfloat162float(h));
    }
}

// ---------------------------------------------------------------------------
// Row softmax over L=4096 on k rows (rows 512..1023 of each batch's qkv)
// ---------------------------------------------------------------------------
__global__ __launch_bounds__(256) void softmax_kernel()
{
    const int row = blockIdx.x;
    const int b = row >> 9;
    const int r = row & 511;
    float* p = g_qkv + (long long)b * QKV_ROWS * LDIM + (long long)(HID + r) * LDIM;

    const int tid = threadIdx.x;
    __shared__ float red[256];

    float4 v[4];
#pragma unroll
    for (int i = 0; i < 4; i++)
        v[i] = *(const float4*)(p + i * 1024 + tid * 4);

    float vmax = -1e30f;
#pragma unroll
    for (int i = 0; i < 4; i++)
        vmax = fmaxf(vmax, fmaxf(fmaxf(v[i].x, v[i].y), fmaxf(v[i].z, v[i].w)));
    red[tid] = vmax;
    __syncthreads();
    for (int s = 128; s > 0; s >>= 1) {
        if (tid < s) red[tid] = fmaxf(red[tid], red[tid + s]);
        __syncthreads();
    }
    vmax = red[0];
    __syncthreads();

    float lsum = 0.0f;
#pragma unroll
    for (int i = 0; i < 4; i++) {
        v[i].x = expf(v[i].x - vmax); lsum += v[i].x;
        v[i].y = expf(v[i].y - vmax); lsum += v[i].y;
        v[i].z = expf(v[i].z - vmax); lsum += v[i].z;
        v[i].w = expf(v[i].w - vmax); lsum += v[i].w;
    }
    red[tid] = lsum;
    __syncthreads();
    for (int s = 128; s > 0; s >>= 1) {
        if (tid < s) red[tid] += red[tid + s];
        __syncthreads();
    }
    const float inv = 1.0f / red[0];

#pragma unroll
    for (int i = 0; i < 4; i++) {
        v[i].x *= inv; v[i].y *= inv; v[i].z *= inv; v[i].w *= inv;
        *(float4*)(p + i * 1024 + tid * 4) = v[i];
    }
}

// ---------------------------------------------------------------------------
// Context partials + reduce + fold
// ---------------------------------------------------------------------------
__global__ __launch_bounds__(256) void context_partial_kernel()
{
    const int split = blockIdx.x;
    const int bh = blockIdx.y;
    const int b = bh >> 3, h = bh & 7;

    const float* kbase = g_qkv + (long long)b * QKV_ROWS * LDIM + (long long)(HID + h * DHEAD) * LDIM;
    const float* vbase = g_qkv + (long long)b * QKV_ROWS * LDIM + (long long)(2 * HID + h * DHEAD) * LDIM;

    __shared__ float Ks[64][65];
    __shared__ float Vs[64][65];

    const int tid = threadIdx.x;
    const int td = (tid >> 4) * 4;
    const int te = (tid & 15) * 4;

    float acc[4][4];
#pragma unroll
    for (int i = 0; i < 4; i++)
#pragma unroll
        for (int j = 0; j < 4; j++) acc[i][j] = 0.0f;

    const int chunk = LDIM / CSPLIT;
    for (int sub = 0; sub < chunk / 64; sub++) {
        const int n0 = split * chunk + sub * 64;
        for (int i = tid; i < 1024; i += 256) {
            const int r = i >> 4, c = (i & 15) * 4;
            float4 kv = *(const float4*)(kbase + (long long)r * LDIM + n0 + c);
            Ks[r][c] = kv.x; Ks[r][c + 1] = kv.y; Ks[r][c + 2] = kv.z; Ks[r][c + 3] = kv.w;
            float4 vv = *(const float4*)(vbase + (long long)r * LDIM + n0 + c);
            Vs[r][c] = vv.x; Vs[r][c + 1] = vv.y; Vs[r][c + 2] = vv.z; Vs[r][c + 3] = vv.w;
        }
        __syncthreads();

#pragma unroll 8
        for (int n = 0; n < 64; n++) {
            float kr[4], vr[4];
#pragma unroll
            for (int i = 0; i < 4; i++) kr[i] = Ks[td + i][n];
#pragma unroll
            for (int j = 0; j < 4; j++) vr[j] = Vs[te + j][n];
#pragma unroll
            for (int i = 0; i < 4; i++)
#pragma unroll
                for (int j = 0; j < 4; j++)
                    acc[i][j] = fmaf(kr[i], vr[j], acc[i][j]);
        }
        __syncthreads();
    }

    float* pout = g_part + ((long long)split * 64 + bh) * (DHEAD * DHEAD);
#pragma unroll
    for (int i = 0; i < 4; i++)
#pragma unroll
        for (int j = 0; j < 4; j++)
            pout[(td + i) * DHEAD + (te + j)] = acc[i][j];
}

__global__ __launch_bounds__(256) void reduce_ctx_kernel()
{
    const int i = blockIdx.x * blockDim.x + threadIdx.x;
    const int total = BATCH * HEADS * DHEAD * DHEAD;
    if (i < total) {
        float s = 0.0f;
#pragma unroll
        for (int sp = 0; sp < CSPLIT; sp++)
            s += g_part[(long long)sp * total + i];
        g_ctx[i] = s;
    }
}

__global__ __launch_bounds__(256) void fold_kernel(const float* __restrict__ w_out)
{
    const int oc = blockIdx.x;
    const int bh = blockIdx.y;
    const int b = bh >> 3, h = bh & 7;

    __shared__ float cs[64][65];
    __shared__ float ws[64][65];

    const int tid = threadIdx.x;
    for (int i = tid; i < 4096; i += 256) {
        const int d = i >> 6, e = i & 63;
        cs[d][e] = g_ctx[((long long)bh * 64 + d) * 64 + e];
    }
    for (int i = tid; i < 4096; i += 256) {
        const int r = i >> 6, e = i & 63;
        ws[r][e] = w_out[(long long)(oc * 64 + r) * CDIM + h * 64 + e];
    }
    __syncthreads();

    const int d = tid & 63;
    const int r0 = (tid >> 6) * 16;
    for (int rr = 0; rr < 16; rr++) {
        float s = 0.0f;
#pragma unroll 8
        for (int e = 0; e < 64; e++)
            s = fmaf(ws[r0 + rr][e], cs[d][e], s);
        g_M[((long long)b * HID + oc * 64 + r0 + rr) * HID + h * 64 + d] = s;
    }
}

// ---------------------------------------------------------------------------
extern "C" void kernel_launch(void* const* d_in, const int* in_sizes, int n_in,
                              void* d_out, int out_size)
{
    const float* x     = (const float*)d_in[0];   // [8, 512, 4096]
    const float* w_qkv = (const float*)d_in[1];   // [1536, 512]
    const float* w_out = (const float*)d_in[2];   // [512, 512]
    const float* b_out = (const float*)d_in[3];   // [512]
    float* out = (float*)d_out;                   // [8, 512, 4096]

    float *p_qkv, *p_M;
    __nv_bfloat16 *p_xthi, *p_xtlo, *p_qthi, *p_qtlo, *p_whi, *p_wlo, *p_Mhi, *p_Mlo;
    cudaGetSymbolAddress((void**)&p_qkv, g_qkv);
    cudaGetSymbolAddress((void**)&p_M, g_M);
    cudaGetSymbolAddress((void**)&p_xthi, g_xt_hi);
    cudaGetSymbolAddress((void**)&p_xtlo, g_xt_lo);
    cudaGetSymbolAddress((void**)&p_qthi, g_qt_hi);
    cudaGetSymbolAddress((void**)&p_qtlo, g_qt_lo);
    cudaGetSymbolAddress((void**)&p_whi, g_w_hi);
    cudaGetSymbolAddress((void**)&p_wlo, g_w_lo);
    cudaGetSymbolAddress((void**)&p_Mhi, g_M_hi);
    cudaGetSymbolAddress((void**)&p_Mlo, g_M_lo);

    cudaFuncSetAttribute(mma_gemm_kernel,
                         cudaFuncAttributeMaxDynamicSharedMemorySize, GEMM_SMEM);

    // 0) split-convert W; transpose+split X
    convert_split_kernel<<<(QKV_ROWS * CDIM + 255) / 256, 256>>>(w_qkv, p_whi, p_wlo, QKV_ROWS * CDIM);
    transpose_convert_kernel<<<dim3(LDIM / 32, CDIM / 32, BATCH), 256>>>(
        x, p_xthi, p_xtlo, CDIM, LDIM,
        (long long)CDIM * LDIM, (long long)LDIM * CDIM);

    // 1) qkv = W @ x  (HMMA tensor cores, split-bf16)
    mma_gemm_kernel<<<dim3(LDIM / 128, QKV_ROWS / 128, BATCH), 256, GEMM_SMEM>>>(
        p_whi, p_wlo, p_xthi, p_xtlo, p_qkv,
        QKV_ROWS, LDIM, CDIM,
        0LL, (long long)LDIM * CDIM, (long long)QKV_ROWS * LDIM, nullptr);

    // 2) transpose+split q (rows 0..511 of qkv per batch)
    transpose_convert_kernel<<<dim3(LDIM / 32, HID / 32, BATCH), 256>>>(
        p_qkv, p_qthi, p_qtlo, HID, LDIM,
        (long long)QKV_ROWS * LDIM, (long long)LDIM * HID);

    // 3) softmax over L on k rows
    softmax_kernel<<<BATCH * HID, 256>>>();

    // 4) context partials + deterministic reduce
    context_partial_kernel<<<dim3(CSPLIT, BATCH * HEADS), 256>>>();
    {
        const int total = BATCH * HEADS * DHEAD * DHEAD;
        reduce_ctx_kernel<<<(total + 255) / 256, 256>>>();
    }

    // 5) fold w_out with context -> per-batch M; split-convert M
    fold_kernel<<<dim3(8, BATCH * HEADS), 256>>>(w_out);
    convert_split_kernel<<<(BATCH * HID * HID + 255) / 256, 256>>>(p_M, p_Mhi, p_Mlo, BATCH * HID * HID);

    // 6) out = M @ q + b_out  (HMMA tensor cores, split-bf16)
    mma_gemm_kernel<<<dim3(LDIM / 128, HID / 128, BATCH), 256, GEMM_SMEM>>>(
        p_Mhi, p_Mlo, p_qthi, p_qtlo, out,
        HID, LDIM, HID,
        (long long)HID * HID, (long long)LDIM * HID, (long long)HID * LDIM, b_out);
}

// round 5
// speedup vs baseline: 2.4713x; 1.0068x over previous
#include <cuda_runtime.h>
#include <cuda_bf16.h>
#include <cstdint>

// Problem constants
#define BATCH 8
#define CDIM 512
#define LDIM 4096
#define HEADS 8
#define DHEAD 64
#define HID 512            // HEADS*DHEAD
#define QKV_ROWS 1536      // 3*HID
#define CSPLIT 32          // n-splits for context partials

// ---------------------------------------------------------------------------
// Scratch (device globals; no allocation allowed)
// ---------------------------------------------------------------------------
__device__ float g_qkv[(size_t)BATCH * QKV_ROWS * LDIM];
__device__ __nv_bfloat16 g_xt_hi[(size_t)BATCH * LDIM * CDIM];
__device__ __nv_bfloat16 g_xt_lo[(size_t)BATCH * LDIM * CDIM];
__device__ __nv_bfloat16 g_qt_hi[(size_t)BATCH * LDIM * HID];
__device__ __nv_bfloat16 g_qt_lo[(size_t)BATCH * LDIM * HID];
__device__ __nv_bfloat16 g_w_hi[(size_t)QKV_ROWS * CDIM];
__device__ __nv_bfloat16 g_w_lo[(size_t)QKV_ROWS * CDIM];
__device__ float g_part[(size_t)CSPLIT * BATCH * HEADS * DHEAD * DHEAD];
__device__ float g_ctx[(size_t)BATCH * HEADS * DHEAD * DHEAD];
__device__ float g_M[(size_t)BATCH * HID * HID];
__device__ __nv_bfloat16 g_M_hi[(size_t)BATCH * HID * HID];
__device__ __nv_bfloat16 g_M_lo[(size_t)BATCH * HID * HID];

// ---------------------------------------------------------------------------
// PTX helpers (baseline sm_103 — NO tcgen05)
// ---------------------------------------------------------------------------
__device__ __forceinline__ uint32_t smem_to_u32(const void* smem_ptr) {
    uint32_t addr;
    asm("{ .reg .u64 tmp; cvta.to.shared.u64 tmp, %1; cvt.u32.u64 %0, tmp; }"
        : "=r"(addr) : "l"(smem_ptr));
    return addr;
}

#define SMEM_SWIZZLE_128B(byte_offset) \
    ((uint32_t)(byte_offset) ^ ((((uint32_t)(byte_offset)) >> 3) & 0x70u))

__device__ __forceinline__ void cp_async16(uint32_t dst, const void* src) {
    asm volatile("cp.async.cg.shared.global [%0], [%1], 16;"
                 :: "r"(dst), "l"(src) : "memory");
}
#define CP_ASYNC_COMMIT() asm volatile("cp.async.commit_group;" ::: "memory")
#define CP_ASYNC_WAIT(n)  asm volatile("cp.async.wait_group %0;" :: "n"(n) : "memory")

__device__ __forceinline__ void ldsm4(uint32_t* r, uint32_t addr) {
    asm volatile("ldmatrix.sync.aligned.m8n8.x4.shared.b16 {%0,%1,%2,%3}, [%4];"
                 : "=r"(r[0]), "=r"(r[1]), "=r"(r[2]), "=r"(r[3]) : "r"(addr));
}

__device__ __forceinline__ void mma_bf16(float* c, const uint32_t* a, const uint32_t* b) {
    asm volatile(
        "mma.sync.aligned.m16n8k16.row.col.f32.bf16.bf16.f32 "
        "{%0,%1,%2,%3}, {%4,%5,%6,%7}, {%8,%9}, {%0,%1,%2,%3};"
        : "+f"(c[0]), "+f"(c[1]), "+f"(c[2]), "+f"(c[3])
        : "r"(a[0]), "r"(a[1]), "r"(a[2]), "r"(a[3]), "r"(b[0]), "r"(b[1]));
}

// ---------------------------------------------------------------------------
// Split-bf16 HMMA GEMM: C[M,N] = A[M,K] @ B[N,K]^T (+row bias)
// Tile 128m x 256n, BK=64, 256 threads (2x4 warps, warp tile 64x64).
// 2-stage cp.async pipeline; 96KB per stage.
// fuse_q: for GEMM1, tiles with bm<512 (q rows) skip the fp32 C store and
// instead write the transposed split-bf16 (qt_hi/qt_lo [N][512]) directly.
// ---------------------------------------------------------------------------
#define STAGE_BYTES 98304
#define OFF_AHI 0
#define OFF_ALO 16384
#define OFF_BHI 32768
#define OFF_BLO 65536
#define GEMM_SMEM (2 * STAGE_BYTES)

__global__ __launch_bounds__(256, 1)
void mma_gemm_kernel(const __nv_bfloat16* __restrict__ Ahi,
                     const __nv_bfloat16* __restrict__ Alo,
                     const __nv_bfloat16* __restrict__ Bhi,
                     const __nv_bfloat16* __restrict__ Blo,
                     float* __restrict__ C,
                     int M, int N, int K,
                     long long sA, long long sB, long long sC,
                     const float* __restrict__ bias,
                     int fuse_q,
                     __nv_bfloat16* __restrict__ Qthi,
                     __nv_bfloat16* __restrict__ Qtlo)
{
    extern __shared__ char smem[];
    const uint32_t smem_base = smem_to_u32(smem);

    const int tid = threadIdx.x;
    const int wid = tid >> 5;
    const int lane = tid & 31;
    const int warp_m = wid >> 2;       // 0..1  (64 rows each)
    const int warp_n = wid & 3;        // 0..3  (64 cols each)

    const int b = blockIdx.z;
    Ahi += (long long)b * sA;  Alo += (long long)b * sA;
    Bhi += (long long)b * sB;  Blo += (long long)b * sB;
    C   += (long long)b * sC;

    const int bm = blockIdx.y * 128;
    const int bn = blockIdx.x * 256;

    float acc[4][8][4];
#pragma unroll
    for (int i = 0; i < 4; i++)
#pragma unroll
        for (int j = 0; j < 8; j++)
#pragma unroll
            for (int r = 0; r < 4; r++) acc[i][j][r] = 0.0f;

    const int nchunk = K >> 6;   // K/64

    // --- chunk loader: A 128 rows, B 256 rows, 64 bf16 (128B) per row ---
    auto load_chunk = [&](int ch, int stage) {
        const int k0 = ch << 6;
        const uint32_t sb = smem_base + stage * STAGE_BYTES;
#pragma unroll
        for (int it = 0; it < 4; it++) {
            const int g = it * 256 + tid;     // 0..1023
            const int row = g >> 3;
            const int gr = g & 7;
            const uint32_t sw = SMEM_SWIZZLE_128B(row * 128 + gr * 16);
            const long long aoff = (long long)(bm + row) * K + k0 + gr * 8;
            cp_async16(sb + OFF_AHI + sw, Ahi + aoff);
            cp_async16(sb + OFF_ALO + sw, Alo + aoff);
        }
#pragma unroll
        for (int it = 0; it < 8; it++) {
            const int g = it * 256 + tid;     // 0..2047
            const int row = g >> 3;
            const int gr = g & 7;
            const uint32_t sw = SMEM_SWIZZLE_128B(row * 128 + gr * 16);
            const long long boff = (long long)(bn + row) * K + k0 + gr * 8;
            cp_async16(sb + OFF_BHI + sw, Bhi + boff);
            cp_async16(sb + OFF_BLO + sw, Blo + boff);
        }
        CP_ASYNC_COMMIT();
    };

    load_chunk(0, 0);

    for (int ch = 0; ch < nchunk; ch++) {
        if (ch + 1 < nchunk) {
            load_chunk(ch + 1, (ch + 1) & 1);
            CP_ASYNC_WAIT(1);
        } else {
            CP_ASYNC_WAIT(0);
        }
        __syncthreads();

        const uint32_t sb = smem_base + (ch & 1) * STAGE_BYTES;
#pragma unroll
        for (int ks = 0; ks < 4; ks++) {
            // B fragments: 8 n8-tiles per warp (4 ldsm.x4 each for hi & lo)
            uint32_t bhi[16], blo[16];
#pragma unroll
            for (int p = 0; p < 4; p++) {
                const int r = warp_n * 64 + p * 16 + ((lane >> 4) & 1) * 8 + (lane & 7);
                const int cb = ks * 32 + ((lane >> 3) & 1) * 16;
                const uint32_t adr = sb + OFF_BHI + SMEM_SWIZZLE_128B(r * 128 + cb);
                ldsm4(bhi + p * 4, adr);
                ldsm4(blo + p * 4, adr + (OFF_BLO - OFF_BHI));
            }
#pragma unroll
            for (int i = 0; i < 4; i++) {
                const int r = warp_m * 64 + i * 16 + ((lane >> 3) & 1) * 8 + (lane & 7);
                const int cb = ks * 32 + ((lane >> 4) & 1) * 16;
                const uint32_t adr = sb + OFF_AHI + SMEM_SWIZZLE_128B(r * 128 + cb);
                uint32_t ahi[4], alo[4];
                ldsm4(ahi, adr);
                ldsm4(alo, adr + (OFF_ALO - OFF_AHI));
#pragma unroll
                for (int j = 0; j < 8; j++) {
                    const uint32_t* bh = bhi + (j >> 1) * 4 + (j & 1) * 2;
                    const uint32_t* bl = blo + (j >> 1) * 4 + (j & 1) * 2;
                    mma_bf16(acc[i][j], ahi, bh);
                    mma_bf16(acc[i][j], ahi, bl);
                    mma_bf16(acc[i][j], alo, bh);
                }
            }
        }
        __syncthreads();
    }

    const bool q_tile = (fuse_q != 0) && (bm < HID);

    if (!q_tile) {
        // Normal epilogue: direct float2 stores (+bias)
#pragma unroll
        for (int i = 0; i < 4; i++) {
            const int m0 = bm + warp_m * 64 + i * 16 + (lane >> 2);
            const float bv0 = bias ? bias[m0] : 0.0f;
            const float bv1 = bias ? bias[m0 + 8] : 0.0f;
#pragma unroll
            for (int j = 0; j < 8; j++) {
                const int n0 = bn + warp_n * 64 + j * 8 + (lane & 3) * 2;
                float2 v0, v1;
                v0.x = acc[i][j][0] + bv0;  v0.y = acc[i][j][1] + bv0;
                v1.x = acc[i][j][2] + bv1;  v1.y = acc[i][j][3] + bv1;
                *(float2*)(C + (long long)m0 * N + n0) = v0;
                *(float2*)(C + (long long)(m0 + 8) * N + n0) = v1;
            }
        }
    } else {
        // Fused q epilogue: per-warp SMEM staging -> transposed split-bf16.
        // qt[n][m] layout, per-batch stride LDIM*HID.
        Qthi += (long long)b * ((long long)LDIM * HID);
        Qtlo += (long long)b * ((long long)LDIM * HID);

        float* st = (float*)smem + (long long)wid * (64 * 68);
        const int g8 = lane >> 2;
        const int t2 = (lane & 3) * 2;
#pragma unroll
        for (int i = 0; i < 4; i++) {
            const int ml0 = i * 16 + g8;
#pragma unroll
            for (int j = 0; j < 8; j++) {
                const int nl0 = j * 8 + t2;
                st[ml0 * 68 + nl0]           = acc[i][j][0];
                st[ml0 * 68 + nl0 + 1]       = acc[i][j][1];
                st[(ml0 + 8) * 68 + nl0]     = acc[i][j][2];
                st[(ml0 + 8) * 68 + nl0 + 1] = acc[i][j][3];
            }
        }
        __syncwarp();

        const int half = lane & 1;            // which 32-m half
        const int mbase = half * 32;
        const int m_g0 = bm + warp_m * 64 + mbase;
#pragma unroll
        for (int set = 0; set < 4; set++) {
            const int nl = set * 16 + (lane >> 1);
            const int n_g = bn + warp_n * 64 + nl;
            __nv_bfloat16 hbuf[32], lbuf[32];
#pragma unroll
            for (int mm = 0; mm < 32; mm++) {
                const float v = st[(mbase + mm) * 68 + nl];
                const __nv_bfloat16 hi = __float2bfloat16(v);
                hbuf[mm] = hi;
                lbuf[mm] = __float2bfloat16(v - __bfloat162float(hi));
            }
            const long long o = (long long)n_g * HID + m_g0;
#pragma unroll
            for (int v4 = 0; v4 < 4; v4++) {
                *(uint4*)(Qthi + o + v4 * 8) = *(uint4*)(hbuf + v4 * 8);
                *(uint4*)(Qtlo + o + v4 * 8) = *(uint4*)(lbuf + v4 * 8);
            }
        }
    }
}

// ---------------------------------------------------------------------------
// Transpose + split-convert: in fp32 [R, L] -> out_hi/out_lo bf16 [L, R]
// ---------------------------------------------------------------------------
__global__ __launch_bounds__(256) void transpose_convert_kernel(
    const float* __restrict__ in,
    __nv_bfloat16* __restrict__ out_hi, __nv_bfloat16* __restrict__ out_lo,
    int R, int L, long long inStride, long long outStride)
{
    const int b = blockIdx.z;
    in += (long long)b * inStride;
    out_hi += (long long)b * outStride;
    out_lo += (long long)b * outStride;

    __shared__ float t[32][33];
    const int r0 = blockIdx.y * 32;
    const int c0 = blockIdx.x * 32;
    const int tx = threadIdx.x & 31;
    const int ty = threadIdx.x >> 5;

#pragma unroll
    for (int i = 0; i < 4; i++)
        t[ty + i * 8][tx] = in[(long long)(r0 + ty + i * 8) * L + c0 + tx];
    __syncthreads();
#pragma unroll
    for (int i = 0; i < 4; i++) {
        const float v = t[tx][ty + i * 8];
        const __nv_bfloat16 hi = __float2bfloat16(v);
        const float lo = v - __bfloat162float(hi);
        const long long o = (long long)(c0 + ty + i * 8) * R + r0 + tx;
        out_hi[o] = hi;
        out_lo[o] = __float2bfloat16(lo);
    }
}

// Plain split-convert
__global__ __launch_bounds__(256) void convert_split_kernel(
    const float* __restrict__ in,
    __nv_bfloat16* __restrict__ hi, __nv_bfloat16* __restrict__ lo, int n)
{
    const int i = blockIdx.x * blockDim.x + threadIdx.x;
    if (i < n) {
        const float v = in[i];
        const __nv_bfloat16 h = __float2bfloat16(v);
        hi[i] = h;
        lo[i] = __float2bfloat16(v - __bfloat162float(h));
    }
}

// ---------------------------------------------------------------------------
// Row softmax over L=4096 on k rows (rows 512..1023 of each batch's qkv)
// ---------------------------------------------------------------------------
__global__ __launch_bounds__(256) void softmax_kernel()
{
    const int row = blockIdx.x;
    const int b = row >> 9;
    const int r = row & 511;
    float* p = g_qkv + (long long)b * QKV_ROWS * LDIM + (long long)(HID + r) * LDIM;

    const int tid = threadIdx.x;
    __shared__ float red[256];

    float4 v[4];
#pragma unroll
    for (int i = 0; i < 4; i++)
        v[i] = *(const float4*)(p + i * 1024 + tid * 4);

    float vmax = -1e30f;
#pragma unroll
    for (int i = 0; i < 4; i++)
        vmax = fmaxf(vmax, fmaxf(fmaxf(v[i].x, v[i].y), fmaxf(v[i].z, v[i].w)));
    red[tid] = vmax;
    __syncthreads();
    for (int s = 128; s > 0; s >>= 1) {
        if (tid < s) red[tid] = fmaxf(red[tid], red[tid + s]);
        __syncthreads();
    }
    vmax = red[0];
    __syncthreads();

    float lsum = 0.0f;
#pragma unroll
    for (int i = 0; i < 4; i++) {
        v[i].x = expf(v[i].x - vmax); lsum += v[i].x;
        v[i].y = expf(v[i].y - vmax); lsum += v[i].y;
        v[i].z = expf(v[i].z - vmax); lsum += v[i].z;
        v[i].w = expf(v[i].w - vmax); lsum += v[i].w;
    }
    red[tid] = lsum;
    __syncthreads();
    for (int s = 128; s > 0; s >>= 1) {
        if (tid < s) red[tid] += red[tid + s];
        __syncthreads();
    }
    const float inv = 1.0f / red[0];

#pragma unroll
    for (int i = 0; i < 4; i++) {
        v[i].x *= inv; v[i].y *= inv; v[i].z *= inv; v[i].w *= inv;
        *(float4*)(p + i * 1024 + tid * 4) = v[i];
    }
}

// ---------------------------------------------------------------------------
// Context partials + reduce + fold
// ---------------------------------------------------------------------------
__global__ __launch_bounds__(256) void context_partial_kernel()
{
    const int split = blockIdx.x;
    const int bh = blockIdx.y;
    const int b = bh >> 3, h = bh & 7;

    const float* kbase = g_qkv + (long long)b * QKV_ROWS * LDIM + (long long)(HID + h * DHEAD) * LDIM;
    const float* vbase = g_qkv + (long long)b * QKV_ROWS * LDIM + (long long)(2 * HID + h * DHEAD) * LDIM;

    __shared__ float Ks[64][65];
    __shared__ float Vs[64][65];

    const int tid = threadIdx.x;
    const int td = (tid >> 4) * 4;
    const int te = (tid & 15) * 4;

    float acc[4][4];
#pragma unroll
    for (int i = 0; i < 4; i++)
#pragma unroll
        for (int j = 0; j < 4; j++) acc[i][j] = 0.0f;

    const int chunk = LDIM / CSPLIT;
    for (int sub = 0; sub < chunk / 64; sub++) {
        const int n0 = split * chunk + sub * 64;
        for (int i = tid; i < 1024; i += 256) {
            const int r = i >> 4, c = (i & 15) * 4;
            float4 kv = *(const float4*)(kbase + (long long)r * LDIM + n0 + c);
            Ks[r][c] = kv.x; Ks[r][c + 1] = kv.y; Ks[r][c + 2] = kv.z; Ks[r][c + 3] = kv.w;
            float4 vv = *(const float4*)(vbase + (long long)r * LDIM + n0 + c);
            Vs[r][c] = vv.x; Vs[r][c + 1] = vv.y; Vs[r][c + 2] = vv.z; Vs[r][c + 3] = vv.w;
        }
        __syncthreads();

#pragma unroll 8
        for (int n = 0; n < 64; n++) {
            float kr[4], vr[4];
#pragma unroll
            for (int i = 0; i < 4; i++) kr[i] = Ks[td + i][n];
#pragma unroll
            for (int j = 0; j < 4; j++) vr[j] = Vs[te + j][n];
#pragma unroll
            for (int i = 0; i < 4; i++)
#pragma unroll
                for (int j = 0; j < 4; j++)
                    acc[i][j] = fmaf(kr[i], vr[j], acc[i][j]);
        }
        __syncthreads();
    }

    float* pout = g_part + ((long long)split * 64 + bh) * (DHEAD * DHEAD);
#pragma unroll
    for (int i = 0; i < 4; i++)
#pragma unroll
        for (int j = 0; j < 4; j++)
            pout[(td + i) * DHEAD + (te + j)] = acc[i][j];
}

__global__ __launch_bounds__(256) void reduce_ctx_kernel()
{
    const int i = blockIdx.x * blockDim.x + threadIdx.x;
    const int total = BATCH * HEADS * DHEAD * DHEAD;
    if (i < total) {
        float s = 0.0f;
#pragma unroll
        for (int sp = 0; sp < CSPLIT; sp++)
            s += g_part[(long long)sp * total + i];
        g_ctx[i] = s;
    }
}

__global__ __launch_bounds__(256) void fold_kernel(const float* __restrict__ w_out)
{
    const int oc = blockIdx.x;
    const int bh = blockIdx.y;
    const int b = bh >> 3, h = bh & 7;

    __shared__ float cs[64][65];
    __shared__ float ws[64][65];

    const int tid = threadIdx.x;
    for (int i = tid; i < 4096; i += 256) {
        const int d = i >> 6, e = i & 63;
        cs[d][e] = g_ctx[((long long)bh * 64 + d) * 64 + e];
    }
    for (int i = tid; i < 4096; i += 256) {
        const int r = i >> 6, e = i & 63;
        ws[r][e] = w_out[(long long)(oc * 64 + r) * CDIM + h * 64 + e];
    }
    __syncthreads();

    const int d = tid & 63;
    const int r0 = (tid >> 6) * 16;
    for (int rr = 0; rr < 16; rr++) {
        float s = 0.0f;
#pragma unroll 8
        for (int e = 0; e < 64; e++)
            s = fmaf(ws[r0 + rr][e], cs[d][e], s);
        g_M[((long long)b * HID + oc * 64 + rr + r0) * HID + h * 64 + d] = s;
    }
}

// ---------------------------------------------------------------------------
extern "C" void kernel_launch(void* const* d_in, const int* in_sizes, int n_in,
                              void* d_out, int out_size)
{
    const float* x     = (const float*)d_in[0];   // [8, 512, 4096]
    const float* w_qkv = (const float*)d_in[1];   // [1536, 512]
    const float* w_out = (const float*)d_in[2];   // [512, 512]
    const float* b_out = (const float*)d_in[3];   // [512]
    float* out = (float*)d_out;                   // [8, 512, 4096]

    float *p_qkv, *p_M;
    __nv_bfloat16 *p_xthi, *p_xtlo, *p_qthi, *p_qtlo, *p_whi, *p_wlo, *p_Mhi, *p_Mlo;
    cudaGetSymbolAddress((void**)&p_qkv, g_qkv);
    cudaGetSymbolAddress((void**)&p_M, g_M);
    cudaGetSymbolAddress((void**)&p_xthi, g_xt_hi);
    cudaGetSymbolAddress((void**)&p_xtlo, g_xt_lo);
    cudaGetSymbolAddress((void**)&p_qthi, g_qt_hi);
    cudaGetSymbolAddress((void**)&p_qtlo, g_qt_lo);
    cudaGetSymbolAddress((void**)&p_whi, g_w_hi);
    cudaGetSymbolAddress((void**)&p_wlo, g_w_lo);
    cudaGetSymbolAddress((void**)&p_Mhi, g_M_hi);
    cudaGetSymbolAddress((void**)&p_Mlo, g_M_lo);

    cudaFuncSetAttribute(mma_gemm_kernel,
                         cudaFuncAttributeMaxDynamicSharedMemorySize, GEMM_SMEM);

    // 0) split-convert W; transpose+split X
    convert_split_kernel<<<(QKV_ROWS * CDIM + 255) / 256, 256>>>(w_qkv, p_whi, p_wlo, QKV_ROWS * CDIM);
    transpose_convert_kernel<<<dim3(LDIM / 32, CDIM / 32, BATCH), 256>>>(
        x, p_xthi, p_xtlo, CDIM, LDIM,
        (long long)CDIM * LDIM, (long long)LDIM * CDIM);

    // 1) qkv = W @ x; q tiles write transposed split-bf16 directly (fused)
    mma_gemm_kernel<<<dim3(LDIM / 256, QKV_ROWS / 128, BATCH), 256, GEMM_SMEM>>>(
        p_whi, p_wlo, p_xthi, p_xtlo, p_qkv,
        QKV_ROWS, LDIM, CDIM,
        0LL, (long long)LDIM * CDIM, (long long)QKV_ROWS * LDIM, nullptr,
        1, p_qthi, p_qtlo);

    // 2) softmax over L on k rows
    softmax_kernel<<<BATCH * HID, 256>>>();

    // 3) context partials + deterministic reduce
    context_partial_kernel<<<dim3(CSPLIT, BATCH * HEADS), 256>>>();
    {
        const int total = BATCH * HEADS * DHEAD * DHEAD;
        reduce_ctx_kernel<<<(total + 255) / 256, 256>>>();
    }

    // 4) fold w_out with context -> per-batch M; split-convert M
    fold_kernel<<<dim3(8, BATCH * HEADS), 256>>>(w_out);
    convert_split_kernel<<<(BATCH * HID * HID + 255) / 256, 256>>>(p_M, p_Mhi, p_Mlo, BATCH * HID * HID);

    // 5) out = M @ q + b_out
    mma_gemm_kernel<<<dim3(LDIM / 256, HID / 128, BATCH), 256, GEMM_SMEM>>>(
        p_Mhi, p_Mlo, p_qthi, p_qtlo, out,
        HID, LDIM, HID,
        (long long)HID * HID, (long long)LDIM * HID, (long long)HID * LDIM, b_out,
        0, nullptr, nullptr);
}